// round 6
// baseline (speedup 1.0000x reference)
#include <cuda_runtime.h>
#include <cuda_bf16.h>
#include <cstdint>

// Problem constants
#define BATCH 1024
#define NN    156
#define NNP   160            // padded rows (GEMM tile)
#define CIN   301
#define CH    128
#define EDGES 1564
#define ETOT  (EDGES + NN)   // 1720
#define MTOT  (BATCH * NN)
#define TS    132            // T row stride (floats), 4-float pad vs 128
#define HS    161            // H_T row stride (floats), odd pad
#define BN_INV_SQRT 0.9999950000374997f

typedef unsigned long long ull;

// ---------------- graph scratch ---------------------------------------------
__device__ int  g_ptr[NN + 1];
__device__ int2 g_edge[ETOT];

// ---------------- packed fp32 helpers ---------------------------------------
__device__ __forceinline__ ull pack2(float lo, float hi) {
    ull r;
    asm("mov.b64 %0, {%1, %2};" : "=l"(r) : "f"(lo), "f"(hi));
    return r;
}
__device__ __forceinline__ void ffma2(ull& d, ull a, ull b) {
    asm("fma.rn.f32x2 %0, %1, %2, %0;" : "+l"(d) : "l"(a), "l"(b));
}

// ---------------- kernel 1: graph preprocessing -> packed CSC ---------------
__global__ void build_kernel(const void* __restrict__ eiv) {
    const int* e32 = (const int*)eiv;
    __shared__ int   is64;
    __shared__ float deg[NN];
    __shared__ float dinv[NN];
    __shared__ int   cnt[NN];
    __shared__ int   base[NN + 1];
    int tid = threadIdx.x;

    if (tid == 0) {
        int all_zero = 1;
        for (int i = 1; i < 129; i += 2)
            if (e32[i] != 0) { all_zero = 0; break; }
        is64 = all_zero;
    }
    if (tid < NN) { deg[tid] = 1.0f; cnt[tid] = 1; }  // self-loop
    __syncthreads();

    const int stride64 = is64;
    auto fetch = [&](int i) -> int {
        int v = e32[i << stride64];
        return min(max(v, 0), NN - 1);
    };

    for (int e = tid; e < EDGES; e += blockDim.x) {
        int cl = fetch(EDGES + e);
        atomicAdd(&deg[cl], 1.0f);
        atomicAdd(&cnt[cl], 1);
    }
    __syncthreads();
    if (tid < NN) dinv[tid] = rsqrtf(deg[tid]);
    if (tid == 0) {
        int run = 0;
        for (int n = 0; n < NN; n++) { base[n] = run; run += cnt[n]; }
        base[NN] = run;
    }
    __syncthreads();
    if (tid <= NN) g_ptr[tid] = base[tid];
    if (tid < NN) cnt[tid] = base[tid];
    __syncthreads();

    for (int e = tid; e < EDGES; e += blockDim.x) {
        int r  = fetch(e);
        int cl = fetch(EDGES + e);
        int pos = atomicAdd(&cnt[cl], 1);
        g_edge[pos] = make_int2(r, __float_as_int(dinv[r] * dinv[cl]));
    }
    __syncthreads();
    for (int n = tid; n < NN; n += blockDim.x) {
        int pos = atomicAdd(&cnt[n], 1);
        g_edge[pos] = make_int2(n, __float_as_int(dinv[n] * dinv[n]));
    }
}

// ---------------- fused per-batch GEMM phase ---------------------------------
// T[m][c] = A[m][k] @ W[k][c].  A: streamed from global x (AG=true, staged
// into As=smHT region, double-buffered) or read directly from smHT[k][m]
// (AG=false).  W: streamed from global into smW double buffer.
// 512 threads: tm = tid>>4 (32 row-threads), tn = tid&15; microtile 5x8.
template<bool AG>
__device__ __forceinline__ void gemm_phase(
    int tid, int K, int ktiles,
    const float* __restrict__ Aglob,
    const float* __restrict__ Wg,
    float* __restrict__ smT,
    float* __restrict__ smHT,
    float* __restrict__ smW)
{
    const int tm  = tid >> 4;
    const int tn  = tid & 15;
    const int wkk = tid >> 5;      // 0..15 (W loads)
    const int wc4 = tid & 31;

    ull acc[5][4];
#pragma unroll
    for (int i = 0; i < 5; i++)
#pragma unroll
        for (int j = 0; j < 4; j++) acc[i][j] = 0ULL;

    float  areg[5];
    float4 wreg;

    // stage tile 0
    if (AG) {
#pragma unroll
        for (int p = 0; p < 5; p++) {
            int idx = tid + p * 512;
            int kk = idx & 15, m = idx >> 4;
            areg[p] = (kk < K && m < NN) ? Aglob[(size_t)m * K + kk] : 0.0f;
        }
    }
    wreg = (wkk < K) ? *(const float4*)(Wg + (size_t)wkk * CH + wc4 * 4)
                     : make_float4(0, 0, 0, 0);
    if (AG) {
#pragma unroll
        for (int p = 0; p < 5; p++) {
            int idx = tid + p * 512;
            smHT[(idx & 15) * HS + (idx >> 4)] = areg[p];
        }
    }
    *(float4*)(smW + wkk * CH + wc4 * 4) = wreg;
    __syncthreads();

    for (int t = 0; t < ktiles; t++) {
        const int cur = t & 1, nxt = cur ^ 1;
        if (t + 1 < ktiles) {
            const int k0n = (t + 1) * 16;
            if (AG) {
#pragma unroll
                for (int p = 0; p < 5; p++) {
                    int idx = tid + p * 512;
                    int kk = idx & 15, m = idx >> 4;
                    int kg = k0n + kk;
                    areg[p] = (kg < K && m < NN) ? Aglob[(size_t)m * K + kg] : 0.0f;
                }
            }
            int kg = k0n + wkk;
            wreg = (kg < K) ? *(const float4*)(Wg + (size_t)kg * CH + wc4 * 4)
                            : make_float4(0, 0, 0, 0);
        }
        const float* Ab = AG ? (smHT + cur * 16 * HS) : (smHT + t * 16 * HS);
        const float* Bb = smW + cur * 16 * CH;
#pragma unroll
        for (int kk = 0; kk < 16; kk++) {
            ull av[5];
#pragma unroll
            for (int i = 0; i < 5; i++) {
                float a = Ab[kk * HS + tm + 32 * i];
                av[i] = pack2(a, a);
            }
            const ull* bp = (const ull*)(Bb + kk * CH + tn * 8);
            ull bv0 = bp[0], bv1 = bp[1], bv2 = bp[2], bv3 = bp[3];
#pragma unroll
            for (int i = 0; i < 5; i++) {
                ffma2(acc[i][0], av[i], bv0);
                ffma2(acc[i][1], av[i], bv1);
                ffma2(acc[i][2], av[i], bv2);
                ffma2(acc[i][3], av[i], bv3);
            }
        }
        if (t + 1 < ktiles) {
            if (AG) {
#pragma unroll
                for (int p = 0; p < 5; p++) {
                    int idx = tid + p * 512;
                    smHT[nxt * 16 * HS + (idx & 15) * HS + (idx >> 4)] = areg[p];
                }
            }
            *(float4*)(smW + nxt * 16 * CH + wkk * CH + wc4 * 4) = wreg;
        }
        __syncthreads();
    }

    // epilogue -> T (row-major, stride TS)
#pragma unroll
    for (int i = 0; i < 5; i++) {
        int m = tm + 32 * i;
        float* tp = smT + m * TS + tn * 8;
#pragma unroll
        for (int j = 0; j < 4; j++) {
            float2 v;
            v.x = __uint_as_float((unsigned)(acc[i][j] & 0xffffffffULL));
            v.y = __uint_as_float((unsigned)(acc[i][j] >> 32));
            *(float2*)(tp + 2 * j) = v;
        }
    }
}

// ---------------- fused aggregation phase ------------------------------------
// Warp-per-dst-row, lane = 4 channels (float4 gather from smT).
// BNRELU: +bias, BN, ReLU, write transposed into smHT[c][n].
// else:   +bias, write to global out (row-major).
template<bool BNRELU>
__device__ __forceinline__ void agg_phase(
    int tid, const float* __restrict__ smT,
    float* __restrict__ smHT, float* __restrict__ gout,
    const int* __restrict__ ptr, const int2* __restrict__ edg,
    const float* __restrict__ bias,
    const float* __restrict__ bnw, const float* __restrict__ bnb)
{
    const int warp = tid >> 5, lane = tid & 31;
    float4 bias4 = ((const float4*)bias)[lane];
    float4 bnw4 = make_float4(0, 0, 0, 0), bnb4 = make_float4(0, 0, 0, 0);
    if (BNRELU) {
        bnw4 = ((const float4*)bnw)[lane];
        bnw4.x *= BN_INV_SQRT; bnw4.y *= BN_INV_SQRT;
        bnw4.z *= BN_INV_SQRT; bnw4.w *= BN_INV_SQRT;
        bnb4 = ((const float4*)bnb)[lane];
    }
    const float4* T4 = (const float4*)smT;   // row stride TS/4 = 33
    for (int n = warp; n < NN; n += 16) {
        int e = ptr[n];
        const int end = ptr[n + 1];
        float4 a0 = make_float4(0, 0, 0, 0);
        float4 a1 = make_float4(0, 0, 0, 0);
        for (; e + 1 < end; e += 2) {
            int2 e0 = edg[e], e1 = edg[e + 1];
            float4 t0 = T4[e0.x * 33 + lane];
            float4 t1 = T4[e1.x * 33 + lane];
            float m0 = __int_as_float(e0.y);
            float m1 = __int_as_float(e1.y);
            a0.x = fmaf(t0.x, m0, a0.x); a0.y = fmaf(t0.y, m0, a0.y);
            a0.z = fmaf(t0.z, m0, a0.z); a0.w = fmaf(t0.w, m0, a0.w);
            a1.x = fmaf(t1.x, m1, a1.x); a1.y = fmaf(t1.y, m1, a1.y);
            a1.z = fmaf(t1.z, m1, a1.z); a1.w = fmaf(t1.w, m1, a1.w);
        }
        if (e < end) {
            int2 e0 = edg[e];
            float4 t0 = T4[e0.x * 33 + lane];
            float m0 = __int_as_float(e0.y);
            a0.x = fmaf(t0.x, m0, a0.x); a0.y = fmaf(t0.y, m0, a0.y);
            a0.z = fmaf(t0.z, m0, a0.z); a0.w = fmaf(t0.w, m0, a0.w);
        }
        float4 v;
        v.x = a0.x + a1.x + bias4.x;
        v.y = a0.y + a1.y + bias4.y;
        v.z = a0.z + a1.z + bias4.z;
        v.w = a0.w + a1.w + bias4.w;
        if (BNRELU) {
            v.x = fmaxf(fmaf(v.x, bnw4.x, bnb4.x), 0.0f);
            v.y = fmaxf(fmaf(v.y, bnw4.y, bnb4.y), 0.0f);
            v.z = fmaxf(fmaf(v.z, bnw4.z, bnb4.z), 0.0f);
            v.w = fmaxf(fmaf(v.w, bnw4.w, bnb4.w), 0.0f);
            const int c = lane * 4;
            smHT[(c + 0) * HS + n] = v.x;
            smHT[(c + 1) * HS + n] = v.y;
            smHT[(c + 2) * HS + n] = v.z;
            smHT[(c + 3) * HS + n] = v.w;
        } else {
            ((float4*)gout)[n * 32 + lane] = v;
        }
    }
}

// ---------------- fused whole-network kernel ---------------------------------
// smem: T[160*132] | HT[128*161] (As aliased, layer0) | W[2*16*128] | edges | ptr
#define SMEM_FUSED ((NNP*TS + CH*HS + 2*16*CH) * 4 + ETOT * 8 + (NN + 1) * 4)

__global__ void __launch_bounds__(512, 1) fused_kernel(
    const float* __restrict__ x,
    const float* __restrict__ W0, const float* __restrict__ b0,
    const float* __restrict__ bnw0, const float* __restrict__ bnb0,
    const float* __restrict__ W1, const float* __restrict__ b1,
    const float* __restrict__ bnw1, const float* __restrict__ bnb1,
    const float* __restrict__ W2, const float* __restrict__ b2,
    float* __restrict__ out)
{
    extern __shared__ float sm[];
    float* smT  = sm;                        // [160*132]
    float* smHT = sm + NNP * TS;             // [128*161]
    float* smW  = smHT + CH * HS;            // [2*16*128]
    int2*  edg  = (int2*)(smW + 2 * 16 * CH);
    int*   ptr  = (int*)(edg + ETOT);

    const int tid = threadIdx.x;
    const int b   = blockIdx.x;

    // stage edge list (covered by first sync inside gemm_phase prologue;
    // first use is much later, after multiple barriers)
    for (int i = tid; i < ETOT; i += 512) edg[i] = g_edge[i];
    if (tid <= NN) ptr[tid] = g_ptr[tid];

    // ---- layer 0: T = x_b @ W0 ; H1 = A-agg(T) + BN + ReLU (transposed) ----
    gemm_phase<true>(tid, CIN, 19, x + (size_t)b * NN * CIN, W0, smT, smHT, smW);
    __syncthreads();
    agg_phase<true>(tid, smT, smHT, nullptr, ptr, edg, b0, bnw0, bnb0);
    // zero-pad H_T columns [156,161) (GEMM reads m up to 159)
    for (int i = tid; i < CH * 5; i += 512)
        smHT[(i & 127) * HS + 156 + (i >> 7)] = 0.0f;
    __syncthreads();

    // ---- layer 1 ----
    gemm_phase<false>(tid, CH, 8, nullptr, W1, smT, smHT, smW);
    __syncthreads();
    agg_phase<true>(tid, smT, smHT, nullptr, ptr, edg, b1, bnw1, bnb1);
    __syncthreads();

    // ---- layer 2 ----
    gemm_phase<false>(tid, CH, 8, nullptr, W2, smT, smHT, smW);
    __syncthreads();
    agg_phase<false>(tid, smT, nullptr, out + (size_t)b * NN * CH,
                     ptr, edg, b2, nullptr, nullptr);
}

// ---------------- launch ----------------------------------------------------
extern "C" void kernel_launch(void* const* d_in, const int* in_sizes, int n_in,
                              void* d_out, int out_size)
{
    const float* x    = (const float*)d_in[0];
    const void*  ei   = d_in[1];
    const float* W0   = (const float*)d_in[2];
    const float* b0   = (const float*)d_in[3];
    const float* bnw0 = (const float*)d_in[4];
    const float* bnb0 = (const float*)d_in[5];
    const float* W1   = (const float*)d_in[6];
    const float* b1   = (const float*)d_in[7];
    const float* bnw1 = (const float*)d_in[8];
    const float* bnb1 = (const float*)d_in[9];
    const float* W2   = (const float*)d_in[10];
    const float* b2   = (const float*)d_in[11];
    float*       out  = (float*)d_out;

    cudaFuncSetAttribute(fused_kernel,
                         cudaFuncAttributeMaxDynamicSharedMemorySize, SMEM_FUSED);

    build_kernel<<<1, 256>>>(ei);
    fused_kernel<<<BATCH, 512, SMEM_FUSED>>>(
        x, W0, b0, bnw0, bnb0, W1, b1, bnw1, bnb1, W2, b2, out);
}